// round 16
// baseline (speedup 1.0000x reference)
#include <cuda_runtime.h>
#include <math.h>

// Problem constants (fixed shapes)
#define DIN   128
#define DHID  256
#define NCLS  16
#define NPROT 512
#define MAXN  50000
#define MAXE  800000

// ---------------- scratch (static device globals; no allocations) ----------
__device__ __align__(16) float g_deg[MAXN];
__device__ __align__(16) float g_dis[MAXN];
__device__ __align__(16) float g_XW[(size_t)MAXN * DHID];    // h @ W (scatter input)
__device__ __align__(16) float g_H [(size_t)MAXN * DHID];    // aggregated / final g
__device__ __align__(16) float g_AncT[DHID * NPROT];         // anchors^T [256][512]
__device__ __align__(16) float g_OP[NPROT * NCLS];           // out_proto
__device__ __align__(16) float g_XREL[(size_t)MAXN * NPROT]; // x_rel scratch
__device__ int g_src[MAXE];
__device__ int g_dst[MAXE];
__device__ int g_prot[NPROT];
__device__ int g_is64;

// ---------------- index dtype probe + normalization ------------------------
// Reference asks for int64 but JAX without x64 silently emits int32. Values
// are in [0, 50000): if buffer is int64 (LE), every odd int32 word is 0.
__global__ void detect_k(const int* __restrict__ ei32) {
    int is64 = 1;
    for (int k = 0; k < 64; k++)
        if (ei32[2 * k + 1] != 0) { is64 = 0; break; }
    g_is64 = is64;
}

__global__ void convert_edges_k(const void* __restrict__ ei, int E) {
    int i = blockIdx.x * blockDim.x + threadIdx.x;
    if (i >= E) return;
    if (g_is64) {
        const long long* p = (const long long*)ei;
        g_src[i] = (int)p[i];
        g_dst[i] = (int)p[E + i];
    } else {
        const int* p = (const int*)ei;
        g_src[i] = p[i];
        g_dst[i] = p[E + i];
    }
}

__global__ void convert_prot_k(const void* __restrict__ prot) {
    int i = blockIdx.x * blockDim.x + threadIdx.x;
    if (i >= NPROT) return;
    g_prot[i] = g_is64 ? (int)((const long long*)prot)[i]
                       : ((const int*)prot)[i];
}

// ---------------- small elementwise kernels --------------------------------
__global__ void fill_deg_k(int n) {
    int i = blockIdx.x * blockDim.x + threadIdx.x;
    if (i < n) g_deg[i] = 1.0f;            // self loop
}

__global__ void degadd_k(int E) {
    int i = blockIdx.x * blockDim.x + threadIdx.x;
    if (i < E) atomicAdd(&g_deg[g_dst[i]], 1.0f);
}

__global__ void dis_k(int n) {
    int i = blockIdx.x * blockDim.x + threadIdx.x;
    if (i < n) g_dis[i] = rsqrtf(g_deg[i]);
}

// H[i,c] = XW[i,c] * dis[i]^2 + b[c]   (self-loop message + bias)
__global__ void init_agg_k(const float* __restrict__ b, int total) {
    int i = blockIdx.x * blockDim.x + threadIdx.x;
    if (i >= total) return;
    int node = i >> 8;          // /256
    int c    = i & 255;
    float d  = g_dis[node];
    g_H[i] = g_XW[i] * d * d + b[c];
}

// ---------------- edge scatter: warp per edge, scalar atomic adds ----------
__global__ void scatter_k(int E) {
    int e = (int)((blockIdx.x * (unsigned)blockDim.x + threadIdx.x) >> 5);
    if (e >= E) return;
    int lane = threadIdx.x & 31;
    int s = g_src[e];
    int d = g_dst[e];
    float nrm = g_dis[s] * g_dis[d];
    const float4* xs = reinterpret_cast<const float4*>(g_XW + (size_t)s * DHID);
    float* hd = g_H + (size_t)d * DHID;
#pragma unroll
    for (int i = 0; i < 2; i++) {
        int c4 = lane + 32 * i;
        float4 v = __ldg(&xs[c4]);
        float* p = hd + c4 * 4;
        atomicAdd(p + 0, v.x * nrm);
        atomicAdd(p + 1, v.y * nrm);
        atomicAdd(p + 2, v.z * nrm);
        atomicAdd(p + 3, v.w * nrm);
    }
}

// ---------------- SGEMM: C[MxN] = op(A[MxK]) @ B[KxN], row-major ------------
#define BM 64
#define BN 64
#define BK 16

// Buffer selector (compile-time): 0 = passed pointer, 1 = g_XW, 2 = g_H,
// 3 = g_AncT, 4 = g_XREL
template <int S>
__device__ __forceinline__ float* selbuf(const float* p) {
    if (S == 1) return (float*)g_XW;
    if (S == 2) return (float*)g_H;
    if (S == 3) return (float*)g_AncT;
    if (S == 4) return (float*)g_XREL;
    return (float*)p;
}

template <bool RELU_A, int AS, int BS, int CS>
__global__ void sgemm_k(const float* Ap, const float* Bp, float* Cp,
                        int M, int N, int K) {
    const float* __restrict__ A = selbuf<AS>(Ap);
    const float* __restrict__ B = selbuf<BS>(Bp);
    float* __restrict__ C = selbuf<CS>(Cp);

    __shared__ float As[BK][BM + 1];
    __shared__ float Bs[BK][BN];
    int t  = threadIdx.x;        // 256 threads
    int tx = t & 15, ty = t >> 4;
    int bm = blockIdx.y * BM;
    int bn = blockIdx.x * BN;

    int arow = t >> 4;           // 0..15
    int acol = t & 15;           // 0..15 (k index)
    int brow = t >> 6;           // 0..3
    int bcol = t & 63;           // 0..63

    float acc[4][4];
#pragma unroll
    for (int i = 0; i < 4; i++)
#pragma unroll
        for (int j = 0; j < 4; j++) acc[i][j] = 0.f;

    for (int k0 = 0; k0 < K; k0 += BK) {
#pragma unroll
        for (int i = 0; i < 4; i++) {
            int r  = arow + 16 * i;
            int gr = bm + r;
            float v = 0.f;
            if (gr < M) v = A[(size_t)gr * K + k0 + acol];
            if (RELU_A) v = fmaxf(v, 0.f);
            As[acol][r] = v;
        }
#pragma unroll
        for (int i = 0; i < 4; i++)
            Bs[brow + 4 * i][bcol] = B[(size_t)(k0 + brow + 4 * i) * N + bn + bcol];
        __syncthreads();
#pragma unroll
        for (int k = 0; k < BK; k++) {
            float a[4], bb[4];
#pragma unroll
            for (int i = 0; i < 4; i++) a[i] = As[k][ty * 4 + i];
#pragma unroll
            for (int j = 0; j < 4; j++) bb[j] = Bs[k][tx * 4 + j];
#pragma unroll
            for (int i = 0; i < 4; i++)
#pragma unroll
                for (int j = 0; j < 4; j++) acc[i][j] += a[i] * bb[j];
        }
        __syncthreads();
    }
#pragma unroll
    for (int i = 0; i < 4; i++) {
        int gr = bm + ty * 4 + i;
        if (gr < M) {
#pragma unroll
            for (int j = 0; j < 4; j++)
                C[(size_t)gr * N + bn + tx * 4 + j] = acc[i][j];
        }
    }
}

// ---------------- double row-normalize (h = H/||H||; g = h/||h||) ----------
__global__ void rownorm_k() {
    int node = blockIdx.x;
    int t = threadIdx.x;
    size_t base = (size_t)node * DHID;
    float v = g_H[base + t];

    __shared__ float red[8];
    __shared__ float bval;

    float s = v * v;
#pragma unroll
    for (int o = 16; o; o >>= 1) s += __shfl_xor_sync(0xffffffffu, s, o);
    if ((t & 31) == 0) red[t >> 5] = s;
    __syncthreads();
    if (t == 0) {
        float q = 0.f;
        for (int i = 0; i < 8; i++) q += red[i];
        bval = sqrtf(q);
    }
    __syncthreads();
    float e = v / bval;
    __syncthreads();                    // red reuse guard

    s = e * e;
#pragma unroll
    for (int o = 16; o; o >>= 1) s += __shfl_xor_sync(0xffffffffu, s, o);
    if ((t & 31) == 0) red[t >> 5] = s;
    __syncthreads();
    if (t == 0) {
        float q = 0.f;
        for (int i = 0; i < 8; i++) q += red[i];
        bval = sqrtf(q);
    }
    __syncthreads();
    g_H[base + t] = e / bval;
}

// ---------------- gather anchors transposed: AncT[k][p] = g[prot[p]][k] ----
__global__ void gatherT_k() {
    int p = blockIdx.x;
    int t = threadIdx.x;
    int node = g_prot[p];
    g_AncT[(size_t)t * NPROT + p] = g_H[(size_t)node * DHID + t];
}

// ---------------- classifier head on prototypes (writes g_OP only) ---------
__global__ void head_k(const float* __restrict__ Wl1, const float* __restrict__ bl1,
                       const float* __restrict__ Wl2, const float* __restrict__ bl2) {
    int p = blockIdx.x;
    int t = threadIdx.x;  // 256
    __shared__ float a[DHID], z[DHID], y[NCLS];
    int node = g_prot[p];
    a[t] = g_H[(size_t)node * DHID + t];
    __syncthreads();

    float acc = bl1[t];
    for (int k = 0; k < DHID; k++) acc += a[k] * Wl1[(size_t)k * DHID + t];
    z[t] = fmaxf(acc, 0.f);
    __syncthreads();

    if (t < NCLS) {
        float yy = bl2[t];
        for (int k = 0; k < DHID; k++) yy += z[k] * Wl2[k * NCLS + t];
        y[t] = yy;
    }
    __syncthreads();
    if (t < NCLS) {
        float m = y[0];
#pragma unroll
        for (int c = 1; c < NCLS; c++) m = fmaxf(m, y[c]);
        float sum = 0.f;
#pragma unroll
        for (int c = 0; c < NCLS; c++) sum += expf(y[c] - m);
        g_OP[p * NCLS + t] = y[t] - m - logf(sum);
    }
}

// ---------------- out = log_softmax(x_rel @ out_proto) ---------------------
__global__ void out_k(float* __restrict__ out, int n) {
    __shared__ float sOPT[NCLS * NPROT];   // transposed, 32KB
    for (int i = threadIdx.x; i < NCLS * NPROT; i += blockDim.x) {
        int c = i >> 9;       // /512
        int p = i & 511;
        sOPT[i] = g_OP[p * NCLS + c];
    }
    __syncthreads();

    int warp = threadIdx.x >> 5;
    int lane = threadIdx.x & 31;
    int node = blockIdx.x * 8 + warp;
    if (node >= n) return;

    const float* xr = g_XREL + (size_t)node * NPROT;
    float lg[NCLS];
#pragma unroll
    for (int c = 0; c < NCLS; c++) lg[c] = 0.f;

    for (int p = lane; p < NPROT; p += 32) {
        float r = xr[p];
#pragma unroll
        for (int c = 0; c < NCLS; c++) lg[c] += r * sOPT[c * NPROT + p];
    }
#pragma unroll
    for (int c = 0; c < NCLS; c++) {
#pragma unroll
        for (int o = 16; o; o >>= 1)
            lg[c] += __shfl_xor_sync(0xffffffffu, lg[c], o);
    }
    float m = lg[0];
#pragma unroll
    for (int c = 1; c < NCLS; c++) m = fmaxf(m, lg[c]);
    float sum = 0.f;
#pragma unroll
    for (int c = 0; c < NCLS; c++) sum += expf(lg[c] - m);
    float lse = m + logf(sum);
    if (lane < NCLS)
        out[(size_t)node * NCLS + lane] = lg[lane] - lse;
}

// ---------------- copy-out helpers (only if d_out holds full tuple) --------
__global__ void copy_xrel_k(float* __restrict__ dst, int total) {
    int i = blockIdx.x * blockDim.x + threadIdx.x;
    if (i < total) dst[i] = g_XREL[i];
}
__global__ void copy_op_k(float* __restrict__ dst) {
    int i = blockIdx.x * blockDim.x + threadIdx.x;
    if (i < NPROT * NCLS) dst[i] = g_OP[i];
}

// ---------------- host driver ----------------------------------------------
extern "C" void kernel_launch(void* const* d_in, const int* in_sizes, int n_in,
                              void* d_out, int out_size) {
    const float* x    = (const float*)d_in[0];
    const void*  ei   = d_in[1];
    const void*  prot = d_in[2];
    int wb = (n_in >= 12) ? 4 : 3;   // skip scalar 'epoch' if present
    const float* W0  = (const float*)d_in[wb + 0];
    const float* b0  = (const float*)d_in[wb + 1];
    const float* W1  = (const float*)d_in[wb + 2];
    const float* b1  = (const float*)d_in[wb + 3];
    const float* Wl1 = (const float*)d_in[wb + 4];
    const float* bl1 = (const float*)d_in[wb + 5];
    const float* Wl2 = (const float*)d_in[wb + 6];
    const float* bl2 = (const float*)d_in[wb + 7];

    int N = in_sizes[0] / DIN;       // 50000
    int E = in_sizes[1] / 2;         // 800000
    float* out_ptr = (float*)d_out;

    // normalize index dtype (int32 vs int64) into g_src/g_dst/g_prot
    detect_k<<<1, 1>>>((const int*)ei);
    convert_edges_k<<<(E + 255) / 256, 256>>>(ei, E);
    convert_prot_k<<<(NPROT + 255) / 256, 256>>>(prot);

    // degree + norm
    fill_deg_k<<<(N + 255) / 256, 256>>>(N);
    degadd_k<<<(E + 255) / 256, 256>>>(E);
    dis_k<<<(N + 255) / 256, 256>>>(N);

    dim3 blk(256);
    int mgrid = (N + BM - 1) / BM;
    int total = N * DHID;

    // layer 0: XW = x @ W0 ; H = self + bias ; scatter
    sgemm_k<false, 0, 0, 1><<<dim3(DHID / BN, mgrid), blk>>>(x, W0, nullptr, N, DHID, DIN);
    init_agg_k<<<(total + 255) / 256, 256>>>(b0, total);
    scatter_k<<<(E * 32 + 255) / 256, 256>>>(E);

    // layer 1: XW = relu(H0) @ W1 ; H = self + bias ; scatter
    sgemm_k<true, 2, 0, 1><<<dim3(DHID / BN, mgrid), blk>>>(nullptr, W1, nullptr, N, DHID, DHID);
    init_agg_k<<<(total + 255) / 256, 256>>>(b1, total);
    scatter_k<<<(E * 32 + 255) / 256, 256>>>(E);

    // g = double row-normalized H1 (in place)
    rownorm_k<<<N, 256>>>();

    // anchors (transposed) + prototype head
    gatherT_k<<<NPROT, DHID>>>();
    head_k<<<NPROT, DHID>>>(Wl1, bl1, Wl2, bl2);

    // x_rel = g @ AncT  (cosine sims; norms fold into g exactly) -> scratch
    sgemm_k<false, 2, 3, 4><<<dim3(NPROT / BN, mgrid), blk>>>(nullptr, nullptr, nullptr,
                                                              N, NPROT, DHID);

    // out = log_softmax(x_rel @ out_proto) -> d_out[0 : N*16]
    out_k<<<(N + 7) / 8, 256>>>(out_ptr, N);

    // If d_out holds the full (out, x_rel, out_proto) tuple, fill the rest.
    size_t need_full = (size_t)N * NCLS + (size_t)N * NPROT + (size_t)NPROT * NCLS;
    if ((size_t)out_size >= need_full) {
        float* xrel_dst = out_ptr + (size_t)N * NCLS;
        float* op_dst   = xrel_dst + (size_t)N * NPROT;
        int xtot = N * NPROT;
        copy_xrel_k<<<(xtot + 255) / 256, 256>>>(xrel_dst, xtot);
        copy_op_k<<<(NPROT * NCLS + 255) / 256, 256>>>(op_dst);
    }
}